// round 1
// baseline (speedup 1.0000x reference)
#include <cuda_runtime.h>

#define BATCH 128
#define SEQ   2048
#define FEAT  64
#define UNITS 64
#define GATES 256   // 4*UNITS
#define OUTD  6

// Scratch: precomputed x@W0 + b0, [B][T][256]  (256 MB + 1KB pad for prefetch over-read)
__device__ float g_pre0[(size_t)BATCH * SEQ * GATES + GATES];

typedef unsigned long long u64;

// ---- packed f32x2 helpers -------------------------------------------------
__device__ __forceinline__ u64 pk(float lo, float hi) {
    u64 r; asm("mov.b64 %0, {%1, %2};" : "=l"(r) : "f"(lo), "f"(hi)); return r;
}
__device__ __forceinline__ void upk(u64 v, float& lo, float& hi) {
    asm("mov.b64 {%0, %1}, %2;" : "=f"(lo), "=f"(hi) : "l"(v));
}
// d.lo += a.lo*b.lo ; d.hi += a.hi*b.hi   (Blackwell packed fp32 FMA, 2x rate)
__device__ __forceinline__ void fma2(u64& d, u64 a, u64 b) {
    asm("fma.rn.f32x2 %0, %1, %2, %0;" : "+l"(d) : "l"(a), "l"(b));
}

// ---- fast activations (MUFU-based, ~1e-7 rel err, overflow-safe) ----------
__device__ __forceinline__ float sig_fast(float x) {
    // x << 0: expf(-x)=inf -> fdividef(1,inf)=0  (correct)
    return __fdividef(1.f, 1.f + __expf(-x));
}
__device__ __forceinline__ float tanh_fast(float x) {
    float e = __expf(fminf(-2.f * x, 30.f));   // clamp avoids inf -> NaN
    return __fdividef(1.f - e, 1.f + e);
}

// ===========================================================================
// Kernel 1: pre0[b][t][j] = sum_k x[b][t][k] * W0[k][j] + b0[j]
// grid: (BATCH, SEQ/128), 256 threads; W0 column in regs, x tile in smem.
// ===========================================================================
__global__ void __launch_bounds__(256) precompute_kernel(
    const float* __restrict__ x, const float* __restrict__ W0,
    const float* __restrict__ b0)
{
    __shared__ __align__(16) float xs[128 * FEAT];   // 32 KB
    const int b  = blockIdx.x;
    const int t0 = blockIdx.y * 128;
    const int j  = threadIdx.x;

    u64 w[32];
#pragma unroll
    for (int m = 0; m < 32; m++)
        w[m] = pk(W0[(2 * m) * GATES + j], W0[(2 * m + 1) * GATES + j]);
    const float bias = b0[j];

    const float* xp = x + ((size_t)b * SEQ + t0) * FEAT;
    for (int i = j; i < 128 * FEAT; i += 256) xs[i] = xp[i];
    __syncthreads();

    float* outp = g_pre0 + ((size_t)b * SEQ + t0) * GATES;
    for (int t = 0; t < 128; t++) {
        u64 a0 = pk(bias, 0.f), a1 = 0ull;
        const u64* hx = (const u64*)(xs + t * FEAT);
#pragma unroll
        for (int m = 0; m < 32; m += 2) {
            fma2(a0, hx[m],     w[m]);
            fma2(a1, hx[m + 1], w[m + 1]);
        }
        float l0, h0, l1, h1; upk(a0, l0, h0); upk(a1, l1, h1);
        outp[(size_t)t * GATES + j] = (l0 + h0) + (l1 + h1);
    }
}

// ===========================================================================
// Kernel 2: persistent recurrence. 128 blocks (1 batch row each), 256 threads
// (1 gate-column each). U0/W1/U1 columns live in registers, k-packed f32x2.
// ===========================================================================
__global__ void __launch_bounds__(256) rnn_kernel(
    const float* __restrict__ U0g, const float* __restrict__ W1g,
    const float* __restrict__ U1g, const float* __restrict__ b1g,
    const float* __restrict__ Wf,  const float* __restrict__ bfv,
    const float* __restrict__ Wo,  const float* __restrict__ bo,
    float* __restrict__ out)
{
    __shared__ __align__(16) float h0s[UNITS];
    __shared__ __align__(16) float h1s[UNITS];
    __shared__ __align__(16) float h2s[UNITS];
    __shared__ float gs[GATES];   // post-activation gate values
    __shared__ float fs[64];      // epilogue dense-1 output

    const int j = threadIdx.x;
    const int b = blockIdx.x;

    // Load weight columns, packed along k (coalesced across threads per k-row).
    u64 u0[32], w1[32], u1[32];
#pragma unroll
    for (int m = 0; m < 32; m++) {
        u0[m] = pk(U0g[(2 * m) * GATES + j], U0g[(2 * m + 1) * GATES + j]);
        w1[m] = pk(W1g[(2 * m) * GATES + j], W1g[(2 * m + 1) * GATES + j]);
        u1[m] = pk(U1g[(2 * m) * GATES + j], U1g[(2 * m + 1) * GATES + j]);
    }
    const float bias1 = b1g[j];
    const bool  isg   = ((j >> 6) == 2);    // columns [128,192) are the g-gate

    float c0 = 0.f, c1 = 0.f, c2 = 0.f;     // cell states (threads < 64)
    if (j < UNITS) { h0s[j] = 0.f; h1s[j] = 0.f; h2s[j] = 0.f; }
    __syncthreads();

    const float* prep = g_pre0 + (size_t)b * SEQ * GATES + j;
    float pre = *prep;

    for (int t = 0; t < SEQ; t++) {
        // ---------------- CELL 0: z = pre0 + h0 @ U0 ----------------
        u64 a0 = pk(pre, 0.f), a1 = 0ull;
        prep += GATES;
        pre = *prep;                         // prefetch next step (padded tail)
        {
            const u64* hp = (const u64*)h0s;
#pragma unroll
            for (int m = 0; m < 32; m += 2) {
                fma2(a0, hp[m],     u0[m]);
                fma2(a1, hp[m + 1], u0[m + 1]);
            }
        }
        float x0, x1, x2, x3;
        upk(a0, x0, x1); upk(a1, x2, x3);
        float z = (x0 + x1) + (x2 + x3);
        gs[j] = isg ? tanh_fast(z) : sig_fast(z);
        __syncthreads();
        if (j < UNITS) {
            float ai = gs[j], af = gs[j + 64], ag = gs[j + 128], ao = gs[j + 192];
            c0 = af * c0 + ai * ag;
            h0s[j] = ao * tanh_fast(c0);
        }
        __syncthreads();

        // ---------------- CELL 1: z = b1 + h0 @ W1 + h1 @ U1 ----------------
        a0 = pk(bias1, 0.f); a1 = 0ull;
        {
            const u64* hp0 = (const u64*)h0s;
            const u64* hp1 = (const u64*)h1s;
#pragma unroll
            for (int m = 0; m < 32; m += 2) {
                fma2(a0, hp0[m],     w1[m]);
                fma2(a1, hp0[m + 1], w1[m + 1]);
            }
#pragma unroll
            for (int m = 0; m < 32; m += 2) {
                fma2(a0, hp1[m],     u1[m]);
                fma2(a1, hp1[m + 1], u1[m + 1]);
            }
        }
        upk(a0, x0, x1); upk(a1, x2, x3);
        z = (x0 + x1) + (x2 + x3);
        gs[j] = isg ? tanh_fast(z) : sig_fast(z);
        __syncthreads();
        if (j < UNITS) {
            float ai = gs[j], af = gs[j + 64], ag = gs[j + 128], ao = gs[j + 192];
            c1 = af * c1 + ai * ag;
            h1s[j] = ao * tanh_fast(c1);
        }
        __syncthreads();

        // ---------------- CELL 2: z = b1 + h1 @ W1 + h2 @ U1 ----------------
        a0 = pk(bias1, 0.f); a1 = 0ull;
        {
            const u64* hp1 = (const u64*)h1s;
            const u64* hp2 = (const u64*)h2s;
#pragma unroll
            for (int m = 0; m < 32; m += 2) {
                fma2(a0, hp1[m],     w1[m]);
                fma2(a1, hp1[m + 1], w1[m + 1]);
            }
#pragma unroll
            for (int m = 0; m < 32; m += 2) {
                fma2(a0, hp2[m],     u1[m]);
                fma2(a1, hp2[m + 1], u1[m + 1]);
            }
        }
        upk(a0, x0, x1); upk(a1, x2, x3);
        z = (x0 + x1) + (x2 + x3);
        gs[j] = isg ? tanh_fast(z) : sig_fast(z);
        __syncthreads();
        if (j < UNITS) {
            float ai = gs[j], af = gs[j + 64], ag = gs[j + 128], ao = gs[j + 192];
            c2 = af * c2 + ai * ag;
            h2s[j] = ao * tanh_fast(c2);
        }
        __syncthreads();
    }

    // ---------------- Epilogue: y = relu(h2 @ Wf + bf) @ Wo + bo ------------
    if (j < 64) {
        float acc = bfv[j];
#pragma unroll
        for (int k = 0; k < 64; k++) acc = fmaf(h2s[k], Wf[k * 64 + j], acc);
        fs[j] = fmaxf(acc, 0.f);
    }
    __syncthreads();
    if (j < OUTD) {
        float acc = bo[j];
#pragma unroll
        for (int k = 0; k < 64; k++) acc = fmaf(fs[k], Wo[k * OUTD + j], acc);
        out[b * OUTD + j] = acc;
    }
}

// ===========================================================================
extern "C" void kernel_launch(void* const* d_in, const int* in_sizes, int n_in,
                              void* d_out, int out_size)
{
    const float* x  = (const float*)d_in[0];
    const float* W0 = (const float*)d_in[1];
    const float* U0 = (const float*)d_in[2];
    const float* b0 = (const float*)d_in[3];
    const float* W1 = (const float*)d_in[4];
    const float* U1 = (const float*)d_in[5];
    const float* b1 = (const float*)d_in[6];
    const float* Wf = (const float*)d_in[7];
    const float* bf = (const float*)d_in[8];
    const float* Wo = (const float*)d_in[9];
    const float* bo = (const float*)d_in[10];

    dim3 pg(BATCH, SEQ / 128);
    precompute_kernel<<<pg, 256>>>(x, W0, b0);
    rnn_kernel<<<BATCH, 256>>>(U0, W1, U1, b1, Wf, bf, Wo, bo, (float*)d_out);
}

// round 2
// speedup vs baseline: 1.0446x; 1.0446x over previous
#include <cuda_runtime.h>

#define BATCH 128
#define SEQ   2048
#define FEAT  64
#define UNITS 64
#define GATES 256   // 4*UNITS
#define OUTD  6

// Precomputed x@W0 + b0, PERMUTED column layout, [B][T][256] (+pad for prefetch over-read)
__device__ float g_pre0[(size_t)BATCH * SEQ * GATES + GATES];

typedef unsigned long long u64;

// ---- packed f32x2 helpers -------------------------------------------------
__device__ __forceinline__ u64 pk(float lo, float hi) {
    u64 r; asm("mov.b64 %0, {%1, %2};" : "=l"(r) : "f"(lo), "f"(hi)); return r;
}
__device__ __forceinline__ void upk(u64 v, float& lo, float& hi) {
    asm("mov.b64 {%0, %1}, %2;" : "=f"(lo), "=f"(hi) : "l"(v));
}
__device__ __forceinline__ void fma2(u64& d, u64 a, u64 b) {
    asm("fma.rn.f32x2 %0, %1, %2, %0;" : "+l"(d) : "l"(a), "l"(b));
}
__device__ __forceinline__ float red4(u64 a, u64 b) {
    float x0, x1, x2, x3; upk(a, x0, x1); upk(b, x2, x3);
    return (x0 + x1) + (x2 + x3);
}

// ---- fast, accurate activations (MUFU EX2/RCP, ~1e-7 rel err) -------------
__device__ __forceinline__ float sig_fast(float x) {
    return __fdividef(1.f, 1.f + __expf(-x));
}
__device__ __forceinline__ float tanh_fast(float x) {
    float e = __expf(fminf(-2.f * x, 30.f));
    return __fdividef(1.f - e, 1.f + e);
}

// Column permutation: thread j <-> gate column (j&3)*64 + (j>>2)
__device__ __forceinline__ int PERM(int j) { return ((j & 3) << 6) + (j >> 2); }

// ===========================================================================
// Kernel 1: pre0[b][t][j] = (x[b][t] @ W0 + b0)[PERM(j)]
// ===========================================================================
__global__ void __launch_bounds__(256) precompute_kernel(
    const float* __restrict__ x, const float* __restrict__ W0,
    const float* __restrict__ b0)
{
    __shared__ __align__(16) float xs[128 * FEAT];   // 32 KB
    const int b   = blockIdx.x;
    const int t0  = blockIdx.y * 128;
    const int j   = threadIdx.x;
    const int col = PERM(j);

    u64 w[32];
#pragma unroll
    for (int m = 0; m < 32; m++)
        w[m] = pk(W0[(2 * m) * GATES + col], W0[(2 * m + 1) * GATES + col]);
    const float bias = b0[col];

    const float4* xp = (const float4*)(x + ((size_t)b * SEQ + t0) * FEAT);
    float4* xsv = (float4*)xs;
    for (int i = j; i < 128 * FEAT / 4; i += 256) xsv[i] = xp[i];
    __syncthreads();

    float* outp = g_pre0 + ((size_t)b * SEQ + t0) * GATES;
    for (int t = 0; t < 128; t++) {
        u64 a0 = pk(bias, 0.f), a1 = 0ull;
        const float4* hx = (const float4*)(xs + t * FEAT);
#pragma unroll
        for (int m = 0; m < 16; m++) {
            float4 q = hx[m];
            fma2(a0, pk(q.x, q.y), w[2 * m]);
            fma2(a1, pk(q.z, q.w), w[2 * m + 1]);
        }
        outp[(size_t)t * GATES + j] = red4(a0, a1);
    }
}

// ===========================================================================
// Kernel 2: persistent recurrence. 128 blocks x 256 threads.
// Thread j: gate g=j&3 of unit u=j>>2. 3 barriers/step.
//   Phase A: z0 = pre + h0_old@U0 ; p1 = b1 + h1_old@U1 ; p2 = b1 + h2_old@U1
//            -> update cell0 (shuffle-local), write h0 (ping-pong buf)
//   Phase B: z1 = p1 + h0@W1 -> update cell1, write h1
//   Phase C: z2 = p2 + h1@W1 -> update cell2, write h2
// ===========================================================================
__global__ void __launch_bounds__(256) rnn_kernel(
    const float* __restrict__ U0g, const float* __restrict__ W1g,
    const float* __restrict__ U1g, const float* __restrict__ b1g,
    const float* __restrict__ Wf,  const float* __restrict__ bfv,
    const float* __restrict__ Wo,  const float* __restrict__ bo,
    float* __restrict__ out)
{
    __shared__ __align__(16) float h0buf[2][UNITS];
    __shared__ __align__(16) float h1s[UNITS];
    __shared__ __align__(16) float h2s[UNITS];
    __shared__ __align__(16) float fs[64];

    const int j   = threadIdx.x;
    const int b   = blockIdx.x;
    const int col = PERM(j);
    const int u   = j >> 2;
    const bool lane0 = ((j & 3) == 0);
    const bool isg   = ((j & 3) == 2);

    // Weight columns in registers, k-packed.
    u64 u0[32], w1[32], u1[32];
#pragma unroll
    for (int m = 0; m < 32; m++) {
        u0[m] = pk(U0g[(2 * m) * GATES + col], U0g[(2 * m + 1) * GATES + col]);
        w1[m] = pk(W1g[(2 * m) * GATES + col], W1g[(2 * m + 1) * GATES + col]);
        u1[m] = pk(U1g[(2 * m) * GATES + col], U1g[(2 * m + 1) * GATES + col]);
    }
    const float bias1 = b1g[col];

    float c0 = 0.f, c1 = 0.f, c2 = 0.f;     // valid only on lane0 threads
    if (j < UNITS) { h0buf[0][j] = 0.f; h1s[j] = 0.f; h2s[j] = 0.f; }
    __syncthreads();

    const float* prep = g_pre0 + (size_t)b * SEQ * GATES + j;
    float pre = *prep;

    for (int t = 0; t < SEQ; t++) {
        const float4* H0r = (const float4*)h0buf[t & 1];
        float*        h0w = h0buf[(t & 1) ^ 1];
        const float4* H1  = (const float4*)h1s;
        const float4* H2  = (const float4*)h2s;

        // ---------------- Phase A ----------------
        u64 z0a = pk(pre, 0.f),   z0b = 0ull;
        u64 p1a = pk(bias1, 0.f), p1b = 0ull;
        u64 p2a = pk(bias1, 0.f), p2b = 0ull;
        prep += GATES;
        pre = *prep;                          // prefetch next step
#pragma unroll
        for (int m = 0; m < 16; m++) {
            float4 q0 = H0r[m];
            fma2(z0a, pk(q0.x, q0.y), u0[2 * m]);
            fma2(z0b, pk(q0.z, q0.w), u0[2 * m + 1]);
            float4 q1 = H1[m];
            fma2(p1a, pk(q1.x, q1.y), u1[2 * m]);
            fma2(p1b, pk(q1.z, q1.w), u1[2 * m + 1]);
            float4 q2 = H2[m];
            fma2(p2a, pk(q2.x, q2.y), u1[2 * m]);
            fma2(p2b, pk(q2.z, q2.w), u1[2 * m + 1]);
        }
        {
            float z = red4(z0a, z0b);
            float a = isg ? tanh_fast(z) : sig_fast(z);
            float v1 = __shfl_xor_sync(0xffffffffu, a, 1);
            float v2 = __shfl_xor_sync(0xffffffffu, a, 2);
            float v3 = __shfl_xor_sync(0xffffffffu, a, 3);
            // valid on lane0 only: i=a, f=v1, cand=v2, o=v3
            c0 = v1 * c0 + a * v2;
            float h = v3 * tanh_fast(c0);
            if (lane0) h0w[u] = h;
        }
        __syncthreads();

        // ---------------- Phase B: z1 = p1 + h0_new @ W1 ----------------
        {
            const float4* H0n = (const float4*)h0w;
#pragma unroll
            for (int m = 0; m < 16; m++) {
                float4 q = H0n[m];
                fma2(p1a, pk(q.x, q.y), w1[2 * m]);
                fma2(p1b, pk(q.z, q.w), w1[2 * m + 1]);
            }
            float z = red4(p1a, p1b);
            float a = isg ? tanh_fast(z) : sig_fast(z);
            float v1 = __shfl_xor_sync(0xffffffffu, a, 1);
            float v2 = __shfl_xor_sync(0xffffffffu, a, 2);
            float v3 = __shfl_xor_sync(0xffffffffu, a, 3);
            c1 = v1 * c1 + a * v2;
            float h = v3 * tanh_fast(c1);
            if (lane0) h1s[u] = h;
        }
        __syncthreads();

        // ---------------- Phase C: z2 = p2 + h1_new @ W1 ----------------
        {
#pragma unroll
            for (int m = 0; m < 16; m++) {
                float4 q = H1[m];
                fma2(p2a, pk(q.x, q.y), w1[2 * m]);
                fma2(p2b, pk(q.z, q.w), w1[2 * m + 1]);
            }
            float z = red4(p2a, p2b);
            float a = isg ? tanh_fast(z) : sig_fast(z);
            float v1 = __shfl_xor_sync(0xffffffffu, a, 1);
            float v2 = __shfl_xor_sync(0xffffffffu, a, 2);
            float v3 = __shfl_xor_sync(0xffffffffu, a, 3);
            c2 = v1 * c2 + a * v2;
            float h = v3 * tanh_fast(c2);
            if (lane0) h2s[u] = h;
        }
        __syncthreads();
    }

    // ---------------- Epilogue: y = relu(h2 @ Wf + bf) @ Wo + bo ------------
    if (j < 64) {
        float acc = bfv[j];
#pragma unroll
        for (int k = 0; k < 64; k++) acc = fmaf(h2s[k], Wf[k * 64 + j], acc);
        fs[j] = fmaxf(acc, 0.f);
    }
    __syncthreads();
    if (j < OUTD) {
        float acc = bo[j];
#pragma unroll
        for (int k = 0; k < 64; k++) acc = fmaf(fs[k], Wo[k * OUTD + j], acc);
        out[b * OUTD + j] = acc;
    }
}

// ===========================================================================
extern "C" void kernel_launch(void* const* d_in, const int* in_sizes, int n_in,
                              void* d_out, int out_size)
{
    const float* x  = (const float*)d_in[0];
    const float* W0 = (const float*)d_in[1];
    const float* U0 = (const float*)d_in[2];
    const float* b0 = (const float*)d_in[3];
    const float* W1 = (const float*)d_in[4];
    const float* U1 = (const float*)d_in[5];
    const float* b1 = (const float*)d_in[6];
    const float* Wf = (const float*)d_in[7];
    const float* bf = (const float*)d_in[8];
    const float* Wo = (const float*)d_in[9];
    const float* bo = (const float*)d_in[10];

    dim3 pg(BATCH, SEQ / 128);
    precompute_kernel<<<pg, 256>>>(x, W0, b0);
    rnn_kernel<<<BATCH, 256>>>(U0, W1, U1, b1, Wf, bf, Wo, bo, (float*)d_out);
}